// round 1
// baseline (speedup 1.0000x reference)
#include <cuda_runtime.h>
#include <math.h>

#define DM      512
#define SEQL    1024
#define NB      16
#define NCH     8192      // NB * DM channels
#define CHB     8         // channels per block
#define TOPK    13
#define NTHREADS 512
#define VS      1028      // padded smem stride for V tile (conflict-free)

// scratch: per-channel top-k weights and indices
__device__ float g_w[NCH * TOPK];
__device__ int   g_i[NCH * TOPK];

__device__ __forceinline__ float2 cmul(float2 a, float2 b) {
    return make_float2(a.x * b.x - a.y * b.y, a.x * b.y + a.y * b.x);
}

extern __shared__ float2 smem_k1[];

// Kernel 1: packed FFT cross-correlation + top-13 + softmax for 8 channels/block
__global__ void __launch_bounds__(NTHREADS) corr_topk_kernel(
    const float* __restrict__ Q, const float* __restrict__ K)
{
    float2* z  = smem_k1;             // [CHB][SEQL] complex work arrays
    float2* tw = smem_k1 + CHB * SEQL; // [512] twiddles W_1024^k, k<512
    __shared__ float topv[CHB][TOPK];
    __shared__ int   topi[CHB][TOPK];

    const int tid = threadIdx.x;
    const int bc0 = blockIdx.x * CHB;       // first flat channel (b*512 + c)
    const int b   = bc0 >> 9;
    const int c0  = bc0 & (DM - 1);
    const size_t base = (size_t)b * SEQL * DM + c0;

    // twiddle table: tw[k] = exp(-2*pi*i*k/1024)
    if (tid < 512) {
        float s, c;
        sincospif(-(float)tid * (1.0f / 512.0f), &s, &c);
        tw[tid] = make_float2(c, s);
    }

    // load z = q + i*k  (8 consecutive d per 32B sector -> coalesced)
    for (int idx = tid; idx < CHB * SEQL; idx += NTHREADS) {
        int d = idx & (CHB - 1);
        int t = idx >> 3;
        size_t off = base + (size_t)t * DM + d;
        z[d * SEQL + t] = make_float2(Q[off], K[off]);
    }
    __syncthreads();

    // forward FFT: radix-2 DIF, natural input -> bit-reversed output
    #pragma unroll
    for (int s = 0; s < 10; ++s) {
        const int half = 512 >> s;
        for (int j = tid; j < CHB * 512; j += NTHREADS) {
            int ch = j >> 9;
            int bf = j & 511;
            int k   = bf & (half - 1);
            int blk = bf >> (9 - s);
            int pos = (blk << (10 - s)) + k;
            float2* zc = z + ch * SEQL;
            float2 a  = zc[pos];
            float2 bb = zc[pos + half];
            float2 w  = tw[k << s];
            zc[pos] = make_float2(a.x + bb.x, a.y + bb.y);
            float2 d2 = make_float2(a.x - bb.x, a.y - bb.y);
            zc[pos + half] = cmul(d2, w);
        }
        __syncthreads();
    }

    // Unpack packed spectra and form cross-spectrum P = Qf * conj(Kf) / N,
    // working directly in bit-reversed positions. Each thread owns one
    // (f, N-f) pair, f in [0, 512], so there are no cross-thread hazards.
    for (int j = tid; j < CHB * 513; j += NTHREADS) {
        int ch = j / 513;
        int f  = j - ch * 513;
        int rf = (int)(__brev((unsigned)f) >> 22);
        int rp = (int)(__brev((unsigned)((SEQL - f) & (SEQL - 1))) >> 22);
        float2* zc = z + ch * SEQL;
        float2 Zf = zc[rf];
        float2 Zp = zc[rp];
        // Qf = (Zf + conj(Zp))/2 ; Kf = (Zf - conj(Zp))/(2i)
        float Qx = 0.5f * (Zf.x + Zp.x);
        float Qy = 0.5f * (Zf.y - Zp.y);
        float Kx = 0.5f * (Zf.y + Zp.y);
        float Ky = -0.5f * (Zf.x - Zp.x);
        const float sc = 1.0f / (float)SEQL;   // fold IFFT 1/N here
        float Px = (Qx * Kx + Qy * Ky) * sc;
        float Py = (Qy * Kx - Qx * Ky) * sc;
        zc[rf] = make_float2(Px, Py);
        zc[rp] = make_float2(Px, -Py);         // conjugate symmetry
    }
    __syncthreads();

    // inverse FFT: radix-2 DIT with conj twiddles, bit-reversed -> natural
    #pragma unroll
    for (int s = 0; s < 10; ++s) {
        const int half = 1 << s;
        for (int j = tid; j < CHB * 512; j += NTHREADS) {
            int ch = j >> 9;
            int bf = j & 511;
            int k   = bf & (half - 1);
            int blk = bf >> s;
            int pos = (blk << (s + 1)) + k;
            float2* zc = z + ch * SEQL;
            float2 w = tw[k << (9 - s)];
            w.y = -w.y;
            float2 a  = zc[pos];
            float2 t2 = cmul(zc[pos + half], w);
            zc[pos]        = make_float2(a.x + t2.x, a.y + t2.y);
            zc[pos + half] = make_float2(a.x - t2.x, a.y - t2.y);
        }
        __syncthreads();
    }

    // top-13 + softmax: one warp per channel (warps 0..7)
    const int wid  = tid >> 5;
    const int lane = tid & 31;
    if (wid < CHB) {
        float2* zc = z + wid * SEQL;
        for (int it = 0; it < TOPK; ++it) {
            float bv = -INFINITY;
            int   bi = 0;
            for (int t = lane; t < SEQL; t += 32) {
                float v = zc[t].x;         // corr is real part
                if (v > bv) { bv = v; bi = t; }
            }
            #pragma unroll
            for (int off = 16; off; off >>= 1) {
                float ov = __shfl_down_sync(0xffffffffu, bv, off);
                int   oi = __shfl_down_sync(0xffffffffu, bi, off);
                if (ov > bv || (ov == bv && oi < bi)) { bv = ov; bi = oi; }
            }
            if (lane == 0) {
                topv[wid][it] = bv;
                topi[wid][it] = bi;
                zc[bi].x = -INFINITY;      // invalidate for next round
            }
            __syncwarp();
        }
        if (lane == 0) {
            float m = -INFINITY;
            #pragma unroll
            for (int i = 0; i < TOPK; ++i) m = fmaxf(m, topv[wid][i]);
            float e[TOPK];
            float s = 0.0f;
            #pragma unroll
            for (int i = 0; i < TOPK; ++i) { e[i] = expf(topv[wid][i] - m); s += e[i]; }
            float inv = 1.0f / s;
            int bc = bc0 + wid;
            #pragma unroll
            for (int i = 0; i < TOPK; ++i) {
                g_w[bc * TOPK + i] = e[i] * inv;
                g_i[bc * TOPK + i] = topi[wid][i];
            }
        }
    }
}

// Kernel 2: time-delay aggregation. 8 channels/block, V tile in smem.
__global__ void __launch_bounds__(NTHREADS) aggregate_kernel(
    const float* __restrict__ V, float* __restrict__ out)
{
    __shared__ float v_sm[CHB * VS];

    const int tid = threadIdx.x;
    const int bc0 = blockIdx.x * CHB;
    const int b   = bc0 >> 9;
    const int c0  = bc0 & (DM - 1);
    const size_t base = (size_t)b * SEQL * DM + c0;

    for (int idx = tid; idx < CHB * SEQL; idx += NTHREADS) {
        int d = idx & (CHB - 1);
        int t = idx >> 3;
        v_sm[d * VS + t] = V[base + (size_t)t * DM + d];
    }
    __syncthreads();

    const int d  = tid & (CHB - 1);
    const int bc = bc0 + d;
    float wreg[TOPK];
    int   ireg[TOPK];
    #pragma unroll
    for (int i = 0; i < TOPK; ++i) {
        wreg[i] = g_w[bc * TOPK + i];
        ireg[i] = g_i[bc * TOPK + i];
    }
    const float* vc = v_sm + d * VS;
    for (int t = tid >> 3; t < SEQL; t += (NTHREADS >> 3)) {
        float acc = 0.0f;
        #pragma unroll
        for (int i = 0; i < TOPK; ++i) {
            int r = ireg[i] + t;
            r = min(r, SEQL - 1);
            acc = fmaf(wreg[i], vc[r], acc);
        }
        out[base + (size_t)t * DM + d] = acc;
    }
}

extern "C" void kernel_launch(void* const* d_in, const int* in_sizes, int n_in,
                              void* d_out, int out_size)
{
    const float* Q = (const float*)d_in[0];
    const float* K = (const float*)d_in[1];
    const float* V = (const float*)d_in[2];
    float* out = (float*)d_out;

    const size_t smem1 = (size_t)(CHB * SEQL + 512) * sizeof(float2); // 69632 B
    cudaFuncSetAttribute(corr_topk_kernel,
                         cudaFuncAttributeMaxDynamicSharedMemorySize, (int)smem1);

    corr_topk_kernel<<<NCH / CHB, NTHREADS, smem1>>>(Q, K);
    aggregate_kernel<<<NCH / CHB, NTHREADS>>>(V, out);
}

// round 3
// speedup vs baseline: 1.2286x; 1.2286x over previous
#include <cuda_runtime.h>
#include <math.h>

#define DM      512
#define SEQL    1024
#define NCH     8192      // 16 * 512 channels
#define CHB     8         // channels per block
#define TOPK    13
#define NTHREADS 512
#define ZS      1026      // padded float2 stride per channel (bank spread)
#define VSTR    1028      // padded float stride for V tile

__device__ __forceinline__ float2 cmul(float2 a, float2 b) {
    return make_float2(a.x * b.x - a.y * b.y, a.x * b.y + a.y * b.x);
}
// a * conj(w)
__device__ __forceinline__ float2 cmulc(float2 a, float2 w) {
    return make_float2(a.x * w.x + a.y * w.y, a.y * w.x - a.x * w.y);
}
// base-4 digit reversal of a 10-bit index
__device__ __forceinline__ int pos4(int f) {
    unsigned y = __brev((unsigned)f) >> 22;           // reverse 10 bits
    return (int)(((y & 0x155u) << 1) | ((y & 0x2AAu) >> 1)); // swap bit pairs
}

extern __shared__ float2 smem_dyn[];

__global__ void __launch_bounds__(NTHREADS, 1) autocorr_fused_kernel(
    const float* __restrict__ Q, const float* __restrict__ K,
    const float* __restrict__ V, float* __restrict__ out)
{
    float2* z  = smem_dyn;                    // [CHB][ZS] complex work
    float2* tw = smem_dyn + CHB * ZS;         // [1024] twiddles W_1024^k
    float*  vf = (float*)(tw + 1024);         // [CHB][VSTR] V tile
    __shared__ float topv[CHB][TOPK];
    __shared__ int   topi[CHB][TOPK];
    __shared__ float w_sh[CHB][TOPK];
    __shared__ int   i_sh[CHB][TOPK];

    const int tid = threadIdx.x;
    const int bc0 = blockIdx.x * CHB;
    const int b   = bc0 >> 9;
    const int c0  = bc0 & (DM - 1);
    const size_t base = (size_t)b * SEQL * DM + c0;

    // twiddles: tw[k] = exp(-2*pi*i*k/1024), full 1024 entries
    {
        float s, c;
        sincospif(-(float)tid * (1.0f / 512.0f), &s, &c);
        tw[tid]       = make_float2(c, s);
        tw[tid + 512] = make_float2(-c, -s);
    }

    // load z = q + i*k via float4; prefetch V into its own smem region
    for (int idx = tid; idx < 2048; idx += NTHREADS) {
        int t  = idx >> 1;
        int d0 = (idx & 1) << 2;
        size_t off = base + (size_t)t * DM + d0;
        float4 q4 = *(const float4*)(Q + off);
        float4 k4 = *(const float4*)(K + off);
        z[(d0 + 0) * ZS + t] = make_float2(q4.x, k4.x);
        z[(d0 + 1) * ZS + t] = make_float2(q4.y, k4.y);
        z[(d0 + 2) * ZS + t] = make_float2(q4.z, k4.z);
        z[(d0 + 3) * ZS + t] = make_float2(q4.w, k4.w);
        float4 v4 = *(const float4*)(V + off);
        vf[(d0 + 0) * VSTR + t] = v4.x;
        vf[(d0 + 1) * VSTR + t] = v4.y;
        vf[(d0 + 2) * VSTR + t] = v4.z;
        vf[(d0 + 3) * VSTR + t] = v4.w;
    }
    __syncthreads();

    // ---- forward FFT: radix-4 DIF, natural -> base4-digit-reversed ----
    #pragma unroll
    for (int s = 0; s < 5; ++s) {
        const int M = 256 >> (2 * s);
        #pragma unroll
        for (int k = 0; k < 4; ++k) {
            int j  = tid + (k << 9);
            int ch = j & 7;
            int bf = j >> 3;                     // [0,256)
            int m   = bf & (M - 1);
            int blk = bf >> (8 - 2 * s);
            float2* zc = z + ch * ZS + (blk << (10 - 2 * s)) + m;
            float2 a0 = zc[0], a1 = zc[M], a2 = zc[2 * M], a3 = zc[3 * M];
            float2 s02p = make_float2(a0.x + a2.x, a0.y + a2.y);
            float2 s02m = make_float2(a0.x - a2.x, a0.y - a2.y);
            float2 s13p = make_float2(a1.x + a3.x, a1.y + a3.y);
            float2 s13m = make_float2(a1.x - a3.x, a1.y - a3.y);
            float2 A0 = make_float2(s02p.x + s13p.x, s02p.y + s13p.y);
            float2 A2 = make_float2(s02p.x - s13p.x, s02p.y - s13p.y);
            float2 A1 = make_float2(s02m.x + s13m.y, s02m.y - s13m.x); // -i*s13m
            float2 A3 = make_float2(s02m.x - s13m.y, s02m.y + s13m.x); // +i*s13m
            int e = m << (2 * s);
            zc[0]     = A0;
            zc[M]     = cmul(A1, tw[e & 1023]);
            zc[2 * M] = cmul(A2, tw[(2 * e) & 1023]);
            zc[3 * M] = cmul(A3, tw[(3 * e) & 1023]);
        }
        __syncthreads();
    }

    // ---- unpack packed spectra, cross-spectrum P = Qf*conj(Kf)/N in digit-reversed domain ----
    for (int j = tid; j < CHB * 513; j += NTHREADS) {
        int ch = j / 513;
        int f  = j - ch * 513;
        int rf = pos4(f);
        int rp = pos4((SEQL - f) & (SEQL - 1));
        float2* zc = z + ch * ZS;
        float2 Zf = zc[rf];
        float2 Zp = zc[rp];
        float Qx = 0.5f * (Zf.x + Zp.x);
        float Qy = 0.5f * (Zf.y - Zp.y);
        float Kx = 0.5f * (Zf.y + Zp.y);
        float Ky = -0.5f * (Zf.x - Zp.x);
        const float sc = 1.0f / (float)SEQL;
        float Px = (Qx * Kx + Qy * Ky) * sc;
        float Py = (Qy * Kx - Qx * Ky) * sc;
        zc[rf] = make_float2(Px, Py);
        zc[rp] = make_float2(Px, -Py);
    }
    __syncthreads();

    // ---- inverse FFT: radix-4 DIT, conj twiddles, digit-reversed -> natural ----
    #pragma unroll
    for (int s = 0; s < 5; ++s) {
        const int M = 1 << (2 * s);
        #pragma unroll
        for (int k = 0; k < 4; ++k) {
            int j  = tid + (k << 9);
            int ch = j & 7;
            int bf = j >> 3;
            int m   = bf & (M - 1);
            int blk = bf >> (2 * s);
            float2* zc = z + ch * ZS + (blk << (2 * s + 2)) + m;
            int e = m << (8 - 2 * s);
            float2 b0 = zc[0];
            float2 b1 = cmulc(zc[M],     tw[e & 1023]);
            float2 b2 = cmulc(zc[2 * M], tw[(2 * e) & 1023]);
            float2 b3 = cmulc(zc[3 * M], tw[(3 * e) & 1023]);
            float2 s02p = make_float2(b0.x + b2.x, b0.y + b2.y);
            float2 s02m = make_float2(b0.x - b2.x, b0.y - b2.y);
            float2 s13p = make_float2(b1.x + b3.x, b1.y + b3.y);
            float2 s13m = make_float2(b1.x - b3.x, b1.y - b3.y);
            zc[0]     = make_float2(s02p.x + s13p.x, s02p.y + s13p.y);
            zc[2 * M] = make_float2(s02p.x - s13p.x, s02p.y - s13p.y);
            zc[M]     = make_float2(s02m.x - s13m.y, s02m.y + s13m.x); // +i*s13m
            zc[3 * M] = make_float2(s02m.x + s13m.y, s02m.y - s13m.x); // -i*s13m
        }
        __syncthreads();
    }

    // ---- top-13 + softmax: one warp per channel (GUARDED: 16 warps, 8 channels) ----
    const int wid  = tid >> 5;
    const int lane = tid & 31;
    if (wid < CHB) {
        float2* zc = z + wid * ZS;
        for (int it = 0; it < TOPK; ++it) {
            float bv = -INFINITY;
            int   bi = 0;
            for (int t = lane; t < SEQL; t += 32) {
                float v = zc[t].x;
                if (v > bv) { bv = v; bi = t; }
            }
            #pragma unroll
            for (int off = 16; off; off >>= 1) {
                float ov = __shfl_down_sync(0xffffffffu, bv, off);
                int   oi = __shfl_down_sync(0xffffffffu, bi, off);
                if (ov > bv || (ov == bv && oi < bi)) { bv = ov; bi = oi; }
            }
            if (lane == 0) {
                topv[wid][it] = bv;
                topi[wid][it] = bi;
                zc[bi].x = -INFINITY;
            }
            __syncwarp();
        }
        if (lane == 0) {
            float m = -INFINITY;
            #pragma unroll
            for (int i = 0; i < TOPK; ++i) m = fmaxf(m, topv[wid][i]);
            float e[TOPK];
            float s = 0.0f;
            #pragma unroll
            for (int i = 0; i < TOPK; ++i) { e[i] = expf(topv[wid][i] - m); s += e[i]; }
            float inv = 1.0f / s;
            #pragma unroll
            for (int i = 0; i < TOPK; ++i) {
                w_sh[wid][i] = e[i] * inv;
                i_sh[wid][i] = topi[wid][i];
            }
        }
    }
    __syncthreads();

    // ---- time-delay aggregation (V already staged in smem) ----
    {
        const int d    = tid & 7;
        const int slot = tid >> 3;                // 0..63, each handles 16 t
        float wr[TOPK];
        int   ir[TOPK];
        #pragma unroll
        for (int i = 0; i < TOPK; ++i) { wr[i] = w_sh[d][i]; ir[i] = i_sh[d][i]; }
        const float* vc = vf + d * VSTR;
        #pragma unroll
        for (int i0 = 0; i0 < 16; i0 += 4) {
            int t = (slot << 4) + i0;
            float a0 = 0.f, a1 = 0.f, a2 = 0.f, a3 = 0.f;
            #pragma unroll
            for (int i = 0; i < TOPK; ++i) {
                int r = ir[i] + t;
                a0 = fmaf(wr[i], vc[min(r,     SEQL - 1)], a0);
                a1 = fmaf(wr[i], vc[min(r + 1, SEQL - 1)], a1);
                a2 = fmaf(wr[i], vc[min(r + 2, SEQL - 1)], a2);
                a3 = fmaf(wr[i], vc[min(r + 3, SEQL - 1)], a3);
            }
            size_t o = base + (size_t)t * DM + d;
            out[o]          = a0;
            out[o + DM]     = a1;
            out[o + 2 * DM] = a2;
            out[o + 3 * DM] = a3;
        }
    }
}

extern "C" void kernel_launch(void* const* d_in, const int* in_sizes, int n_in,
                              void* d_out, int out_size)
{
    const float* Q = (const float*)d_in[0];
    const float* K = (const float*)d_in[1];
    const float* V = (const float*)d_in[2];
    float* out = (float*)d_out;

    const size_t smem = (size_t)(CHB * ZS + 1024) * sizeof(float2)
                      + (size_t)(CHB * VSTR) * sizeof(float);   // 106,752 B
    cudaFuncSetAttribute(autocorr_fused_kernel,
                         cudaFuncAttributeMaxDynamicSharedMemorySize, (int)smem);
    autocorr_fused_kernel<<<NCH / CHB, NTHREADS, smem>>>(Q, K, V, out);
}

// round 4
// speedup vs baseline: 1.6581x; 1.3496x over previous
#include <cuda_runtime.h>
#include <math.h>

#define DM      512
#define SEQL    1024
#define NCH     8192
#define CHB     8
#define TOPK    13
#define NTHREADS 512
#define ZS      1025      // float2 stride per channel (bank offset between channels)
#define VSTR    1028      // padded float stride for V tile

__device__ __forceinline__ float2 cmul(float2 a, float2 b) {
    return make_float2(a.x * b.x - a.y * b.y, a.x * b.y + a.y * b.x);
}
// XOR swizzle within a 1024-element channel region
__device__ __forceinline__ int sw(int p) { return p ^ ((p >> 4) & 15); }
// storage position of frequency f after (16,16,4)-DIF: f = f0 + 16*f1 + 256*f2
__device__ __forceinline__ int posf(int f) {
    return ((f & 15) << 6) | (((f >> 4) & 15) << 2) | (f >> 8);
}

// powers W[1..15] from w1 via squaring chain
__device__ __forceinline__ void twpow(float2 w1, float2* W) {
    W[1] = w1;
    W[2] = cmul(w1, w1);
    W[4] = cmul(W[2], W[2]);
    W[8] = cmul(W[4], W[4]);
    W[3] = cmul(W[2], W[1]);
    W[5] = cmul(W[4], W[1]);
    W[6] = cmul(W[4], W[2]);
    W[7] = cmul(W[4], W[3]);
    W[9]  = cmul(W[8], W[1]);
    W[10] = cmul(W[8], W[2]);
    W[11] = cmul(W[8], W[3]);
    W[12] = cmul(W[8], W[4]);
    W[13] = cmul(W[8], W[5]);
    W[14] = cmul(W[8], W[6]);
    W[15] = cmul(W[8], W[7]);
}

#define C16 0.9238795325112867f
#define S16 0.3826834323650898f
#define R22 0.7071067811865476f

// forward 4-pt DFT (W4 = -i)
__device__ __forceinline__ void dft4f(float2 x0, float2 x1, float2 x2, float2 x3,
                                      float2& y0, float2& y1, float2& y2, float2& y3) {
    float2 sp = make_float2(x0.x + x2.x, x0.y + x2.y);
    float2 sm = make_float2(x0.x - x2.x, x0.y - x2.y);
    float2 tp = make_float2(x1.x + x3.x, x1.y + x3.y);
    float2 tm = make_float2(x1.x - x3.x, x1.y - x3.y);
    y0 = make_float2(sp.x + tp.x, sp.y + tp.y);
    y2 = make_float2(sp.x - tp.x, sp.y - tp.y);
    y1 = make_float2(sm.x + tm.y, sm.y - tm.x);   // sm - i*tm
    y3 = make_float2(sm.x - tm.y, sm.y + tm.x);   // sm + i*tm
}
// inverse 4-pt DFT (W4 = +i)
__device__ __forceinline__ void dft4i(float2 x0, float2 x1, float2 x2, float2 x3,
                                      float2& y0, float2& y1, float2& y2, float2& y3) {
    float2 sp = make_float2(x0.x + x2.x, x0.y + x2.y);
    float2 sm = make_float2(x0.x - x2.x, x0.y - x2.y);
    float2 tp = make_float2(x1.x + x3.x, x1.y + x3.y);
    float2 tm = make_float2(x1.x - x3.x, x1.y - x3.y);
    y0 = make_float2(sp.x + tp.x, sp.y + tp.y);
    y2 = make_float2(sp.x - tp.x, sp.y - tp.y);
    y1 = make_float2(sm.x - tm.y, sm.y + tm.x);   // sm + i*tm
    y3 = make_float2(sm.x + tm.y, sm.y - tm.x);   // sm - i*tm
}

// 16-pt DFT in registers, natural order in/out. fwd: e^{-2pi i a f/16}
__device__ __forceinline__ void dft16f(float2* v) {
    const float2 W[10] = {
        { 1.f, 0.f}, { C16,-S16}, { R22,-R22}, { S16,-C16}, { 0.f,-1.f},
        {-S16,-C16}, {-R22,-R22}, {-C16,-S16}, {-1.f, 0.f}, {-C16, S16}
    };
    float2 u[16];
    #pragma unroll
    for (int a0 = 0; a0 < 4; ++a0) {
        float2 t0, t1, t2, t3;
        dft4f(v[a0], v[a0 + 4], v[a0 + 8], v[a0 + 12], t0, t1, t2, t3);
        u[a0 * 4 + 0] = t0;
        u[a0 * 4 + 1] = cmul(t1, W[a0]);
        u[a0 * 4 + 2] = cmul(t2, W[2 * a0]);
        u[a0 * 4 + 3] = cmul(t3, W[3 * a0]);
    }
    #pragma unroll
    for (int fl = 0; fl < 4; ++fl) {
        float2 y0, y1, y2, y3;
        dft4f(u[0 * 4 + fl], u[1 * 4 + fl], u[2 * 4 + fl], u[3 * 4 + fl], y0, y1, y2, y3);
        v[fl]      = y0;
        v[fl + 4]  = y1;
        v[fl + 8]  = y2;
        v[fl + 12] = y3;
    }
}
// inverse 16-pt: e^{+2pi i a f/16}, unnormalized
__device__ __forceinline__ void dft16i(float2* v) {
    const float2 W[10] = {
        { 1.f, 0.f}, { C16, S16}, { R22, R22}, { S16, C16}, { 0.f, 1.f},
        {-S16, C16}, {-R22, R22}, {-C16, S16}, {-1.f, 0.f}, {-C16,-S16}
    };
    float2 u[16];
    #pragma unroll
    for (int fl = 0; fl < 4; ++fl) {
        float2 t0, t1, t2, t3;
        dft4i(v[fl], v[fl + 4], v[fl + 8], v[fl + 12], t0, t1, t2, t3);
        u[fl * 4 + 0] = t0;
        u[fl * 4 + 1] = cmul(t1, W[fl]);
        u[fl * 4 + 2] = cmul(t2, W[2 * fl]);
        u[fl * 4 + 3] = cmul(t3, W[3 * fl]);
    }
    #pragma unroll
    for (int a0 = 0; a0 < 4; ++a0) {
        float2 y0, y1, y2, y3;
        dft4i(u[0 * 4 + a0], u[1 * 4 + a0], u[2 * 4 + a0], u[3 * 4 + a0], y0, y1, y2, y3);
        v[a0]      = y0;
        v[a0 + 4]  = y1;
        v[a0 + 8]  = y2;
        v[a0 + 12] = y3;
    }
}

extern __shared__ float2 smem_dyn[];

__global__ void __launch_bounds__(NTHREADS, 1) autocorr_fused_kernel(
    const float* __restrict__ Q, const float* __restrict__ K,
    const float* __restrict__ V, float* __restrict__ out)
{
    float2* z = smem_dyn;                     // [CHB][ZS]
    float*  vf = (float*)(smem_dyn + CHB * ZS); // [CHB][VSTR]
    __shared__ float2 cand[CHB][2][2];        // [ch][warp][parity]
    __shared__ float  w_sh[CHB][TOPK + 1];
    __shared__ int    i_sh[CHB][TOPK];

    const int tid = threadIdx.x;
    const int ch  = tid >> 6;                 // channel of this thread (FFT phases)
    const int u   = tid & 63;                 // lane within channel (0..63)
    float2* zc = z + ch * ZS;

    const int bc0 = blockIdx.x * CHB;
    const int b   = bc0 >> 9;
    const int c0  = bc0 & (DM - 1);
    const size_t base = (size_t)b * SEQL * DM + c0;

    // ---- load: z = q + i*k (swizzled), prefetch V ----
    for (int idx = tid; idx < 2048; idx += NTHREADS) {
        int t  = idx >> 1;
        int d0 = (idx & 1) << 2;
        size_t off = base + (size_t)t * DM + d0;
        float4 q4 = *(const float4*)(Q + off);
        float4 k4 = *(const float4*)(K + off);
        int st = sw(t);
        z[(d0 + 0) * ZS + st] = make_float2(q4.x, k4.x);
        z[(d0 + 1) * ZS + st] = make_float2(q4.y, k4.y);
        z[(d0 + 2) * ZS + st] = make_float2(q4.z, k4.z);
        z[(d0 + 3) * ZS + st] = make_float2(q4.w, k4.w);
        float4 v4 = *(const float4*)(V + off);
        vf[(d0 + 0) * VSTR + t] = v4.x;
        vf[(d0 + 1) * VSTR + t] = v4.y;
        vf[(d0 + 2) * VSTR + t] = v4.z;
        vf[(d0 + 3) * VSTR + t] = v4.w;
    }
    __syncthreads();

    // ---- P1: radix-16 over stride 64, twiddle W1024^{u*f0} ----
    {
        float2 v[16];
        #pragma unroll
        for (int a = 0; a < 16; ++a) v[a] = zc[sw(u + 64 * a)];
        dft16f(v);
        float s, c;
        sincospif((float)u * (1.0f / 512.0f), &s, &c);
        float2 W[16];
        twpow(make_float2(c, -s), W);
        #pragma unroll
        for (int f = 1; f < 16; ++f) v[f] = cmul(v[f], W[f]);
        #pragma unroll
        for (int f = 0; f < 16; ++f) zc[sw(u + 64 * f)] = v[f];
    }
    __syncthreads();

    // ---- P2: within 64-blocks, radix-16 over stride 4, twiddle W64^{m'*f1} ----
    {
        const int blk = u >> 2;
        const int mp  = u & 3;
        const int bas = 64 * blk + mp;
        float2 v[16];
        #pragma unroll
        for (int a = 0; a < 16; ++a) v[a] = zc[sw(bas + 4 * a)];
        dft16f(v);
        float s, c;
        sincospif((float)mp * (1.0f / 32.0f), &s, &c);
        float2 W[16];
        twpow(make_float2(c, -s), W);
        #pragma unroll
        for (int f = 1; f < 16; ++f) v[f] = cmul(v[f], W[f]);
        #pragma unroll
        for (int f = 0; f < 16; ++f) zc[sw(bas + 4 * f)] = v[f];
    }
    __syncthreads();

    // ---- P3: radix-4 on consecutive quads (no twiddle) ----
    #pragma unroll
    for (int s4 = 0; s4 < 4; ++s4) {
        int g = u + 64 * s4;
        int p = 4 * g;
        float2 x0 = zc[sw(p)], x1 = zc[sw(p + 1)], x2 = zc[sw(p + 2)], x3 = zc[sw(p + 3)];
        float2 y0, y1, y2, y3;
        dft4f(x0, x1, x2, x3, y0, y1, y2, y3);
        zc[sw(p)] = y0; zc[sw(p + 1)] = y1; zc[sw(p + 2)] = y2; zc[sw(p + 3)] = y3;
    }
    __syncthreads();

    // ---- spectrum: unpack packed FFT, P = Qf*conj(Kf)/N ----
    {
        const float scl = 1.0f / (float)SEQL;
        #pragma unroll
        for (int s8 = 0; s8 < 8; ++s8) {
            int f  = u + 64 * s8;               // 0..511
            int fp = (SEQL - f) & (SEQL - 1);
            int pf = sw(posf(f));
            int pp = sw(posf(fp));
            float2 Zf = zc[pf];
            float2 Zp = zc[pp];
            float Qx = 0.5f * (Zf.x + Zp.x);
            float Qy = 0.5f * (Zf.y - Zp.y);
            float Kx = 0.5f * (Zf.y + Zp.y);
            float Ky = -0.5f * (Zf.x - Zp.x);
            float Px = (Qx * Kx + Qy * Ky) * scl;
            float Py = (Qy * Kx - Qx * Ky) * scl;
            zc[pf] = make_float2(Px, Py);
            zc[pp] = make_float2(Px, -Py);
        }
        if (u == 0) {                            // f = 512 (self-paired)
            int pf = sw(posf(512));
            float2 Zf = zc[pf];
            float Qx = Zf.x, Kx = Zf.y;          // both real at Nyquist
            zc[pf] = make_float2(Qx * Kx * scl, 0.0f);
        }
    }
    __syncthreads();

    // ---- IP3: inverse radix-4 on quads ----
    #pragma unroll
    for (int s4 = 0; s4 < 4; ++s4) {
        int g = u + 64 * s4;
        int p = 4 * g;
        float2 x0 = zc[sw(p)], x1 = zc[sw(p + 1)], x2 = zc[sw(p + 2)], x3 = zc[sw(p + 3)];
        float2 y0, y1, y2, y3;
        dft4i(x0, x1, x2, x3, y0, y1, y2, y3);
        zc[sw(p)] = y0; zc[sw(p + 1)] = y1; zc[sw(p + 2)] = y2; zc[sw(p + 3)] = y3;
    }
    __syncthreads();

    // ---- IP2: conj twiddle then inverse radix-16 stride 4 ----
    {
        const int blk = u >> 2;
        const int mp  = u & 3;
        const int bas = 64 * blk + mp;
        float2 v[16];
        #pragma unroll
        for (int f = 0; f < 16; ++f) v[f] = zc[sw(bas + 4 * f)];
        float s, c;
        sincospif((float)mp * (1.0f / 32.0f), &s, &c);
        float2 W[16];
        twpow(make_float2(c, s), W);
        #pragma unroll
        for (int f = 1; f < 16; ++f) v[f] = cmul(v[f], W[f]);
        dft16i(v);
        #pragma unroll
        for (int a = 0; a < 16; ++a) zc[sw(bas + 4 * a)] = v[a];
    }
    __syncthreads();

    // ---- IP1: conj twiddle then inverse radix-16 stride 64; results stay in regs ----
    float re[16];
    {
        float2 v[16];
        #pragma unroll
        for (int f = 0; f < 16; ++f) v[f] = zc[sw(u + 64 * f)];
        float s, c;
        sincospif((float)u * (1.0f / 512.0f), &s, &c);
        float2 W[16];
        twpow(make_float2(c, s), W);
        #pragma unroll
        for (int f = 1; f < 16; ++f) v[f] = cmul(v[f], W[f]);
        dft16i(v);
        #pragma unroll
        for (int a = 0; a < 16; ++a) re[a] = v[a].x;   // time index = u + 64a
    }

    // ---- top-13: register-resident, 2 warps per channel, named barriers ----
    {
        const int lane = tid & 31;
        const int wih  = (u >> 5) & 1;       // which warp of the channel pair
        // local argmax over 16 register values
        float lv = re[0]; int lj = 0;
        #pragma unroll
        for (int j2 = 1; j2 < 16; ++j2)
            if (re[j2] > lv) { lv = re[j2]; lj = j2; }
        int li = u + 64 * lj;

        #pragma unroll 1
        for (int r = 0; r < TOPK; ++r) {
            float bv = lv; int bi = li;
            #pragma unroll
            for (int off = 16; off; off >>= 1) {
                float ov = __shfl_down_sync(0xffffffffu, bv, off);
                int   oi = __shfl_down_sync(0xffffffffu, bi, off);
                if (ov > bv || (ov == bv && oi < bi)) { bv = ov; bi = oi; }
            }
            bv = __shfl_sync(0xffffffffu, bv, 0);
            bi = __shfl_sync(0xffffffffu, bi, 0);
            int par = r & 1;
            if (lane == 0)
                cand[ch][wih][par] = make_float2(bv, __int_as_float(bi));
            asm volatile("bar.sync %0, %1;" :: "r"(ch + 1), "r"(64) : "memory");
            float2 c0v = cand[ch][0][par];
            float2 c1v = cand[ch][1][par];
            float wv; int wi;
            int i0 = __float_as_int(c0v.y), i1 = __float_as_int(c1v.y);
            if (c1v.x > c0v.x || (c1v.x == c0v.x && i1 < i0)) { wv = c1v.x; wi = i1; }
            else                                              { wv = c0v.x; wi = i0; }
            if (u == 0) { w_sh[ch][r] = wv; i_sh[ch][r] = wi; }
            if ((wi & 63) == u) {
                re[wi >> 6] = -INFINITY;
                lv = re[0]; lj = 0;
                #pragma unroll
                for (int j2 = 1; j2 < 16; ++j2)
                    if (re[j2] > lv) { lv = re[j2]; lj = j2; }
                li = u + 64 * lj;
            }
        }
        asm volatile("bar.sync %0, %1;" :: "r"(ch + 1), "r"(64) : "memory");
        if (u == 0) {
            float m = -INFINITY;
            #pragma unroll
            for (int i = 0; i < TOPK; ++i) m = fmaxf(m, w_sh[ch][i]);
            float e[TOPK]; float ssum = 0.0f;
            #pragma unroll
            for (int i = 0; i < TOPK; ++i) { e[i] = expf(w_sh[ch][i] - m); ssum += e[i]; }
            float inv = 1.0f / ssum;
            #pragma unroll
            for (int i = 0; i < TOPK; ++i) w_sh[ch][i] = e[i] * inv;
        }
    }
    __syncthreads();

    // ---- time-delay aggregation ----
    {
        const int d    = tid & 7;
        const int slot = tid >> 3;
        float wr[TOPK];
        int   ir[TOPK];
        #pragma unroll
        for (int i = 0; i < TOPK; ++i) { wr[i] = w_sh[d][i]; ir[i] = i_sh[d][i]; }
        const float* vc = vf + d * VSTR;
        #pragma unroll
        for (int i0 = 0; i0 < 16; i0 += 4) {
            int t = (slot << 4) + i0;
            float a0 = 0.f, a1 = 0.f, a2 = 0.f, a3 = 0.f;
            #pragma unroll
            for (int i = 0; i < TOPK; ++i) {
                int r = ir[i] + t;
                a0 = fmaf(wr[i], vc[min(r,     SEQL - 1)], a0);
                a1 = fmaf(wr[i], vc[min(r + 1, SEQL - 1)], a1);
                a2 = fmaf(wr[i], vc[min(r + 2, SEQL - 1)], a2);
                a3 = fmaf(wr[i], vc[min(r + 3, SEQL - 1)], a3);
            }
            size_t o = base + (size_t)t * DM + d;
            out[o]          = a0;
            out[o + DM]     = a1;
            out[o + 2 * DM] = a2;
            out[o + 3 * DM] = a3;
        }
    }
}

extern "C" void kernel_launch(void* const* d_in, const int* in_sizes, int n_in,
                              void* d_out, int out_size)
{
    const float* Q = (const float*)d_in[0];
    const float* K = (const float*)d_in[1];
    const float* V = (const float*)d_in[2];
    float* out = (float*)d_out;

    const size_t smem = (size_t)(CHB * ZS) * sizeof(float2)
                      + (size_t)(CHB * VSTR) * sizeof(float);   // 98,496 B
    cudaFuncSetAttribute(autocorr_fused_kernel,
                         cudaFuncAttributeMaxDynamicSharedMemorySize, (int)smem);
    autocorr_fused_kernel<<<NCH / CHB, NTHREADS, smem>>>(Q, K, V, out);
}

// round 6
// speedup vs baseline: 1.7177x; 1.0360x over previous
#include <cuda_runtime.h>
#include <math.h>

#define DM      512
#define SEQL    1024
#define NCH     8192
#define CHB     8
#define TOPK    13
#define NTHREADS 512
#define ZS      1025      // float2 stride per channel
#define VSTR    1028      // padded float stride for V tile

__device__ __forceinline__ float2 cmul(float2 a, float2 b) {
    return make_float2(a.x * b.x - a.y * b.y, a.x * b.y + a.y * b.x);
}
// XOR swizzle within a 1024-element channel region
__device__ __forceinline__ int sw(int p) { return p ^ ((p >> 4) & 15); }

// powers W[1..15] from w1 via squaring chain
__device__ __forceinline__ void twpow(float2 w1, float2* W) {
    W[1] = w1;
    W[2] = cmul(w1, w1);
    W[4] = cmul(W[2], W[2]);
    W[8] = cmul(W[4], W[4]);
    W[3] = cmul(W[2], W[1]);
    W[5] = cmul(W[4], W[1]);
    W[6] = cmul(W[4], W[2]);
    W[7] = cmul(W[4], W[3]);
    W[9]  = cmul(W[8], W[1]);
    W[10] = cmul(W[8], W[2]);
    W[11] = cmul(W[8], W[3]);
    W[12] = cmul(W[8], W[4]);
    W[13] = cmul(W[8], W[5]);
    W[14] = cmul(W[8], W[6]);
    W[15] = cmul(W[8], W[7]);
}

#define C16 0.9238795325112867f
#define S16 0.3826834323650898f
#define R22 0.7071067811865476f

// forward 4-pt DFT (W4 = -i)
__device__ __forceinline__ void dft4f(float2 x0, float2 x1, float2 x2, float2 x3,
                                      float2& y0, float2& y1, float2& y2, float2& y3) {
    float2 sp = make_float2(x0.x + x2.x, x0.y + x2.y);
    float2 sm = make_float2(x0.x - x2.x, x0.y - x2.y);
    float2 tp = make_float2(x1.x + x3.x, x1.y + x3.y);
    float2 tm = make_float2(x1.x - x3.x, x1.y - x3.y);
    y0 = make_float2(sp.x + tp.x, sp.y + tp.y);
    y2 = make_float2(sp.x - tp.x, sp.y - tp.y);
    y1 = make_float2(sm.x + tm.y, sm.y - tm.x);   // sm - i*tm
    y3 = make_float2(sm.x - tm.y, sm.y + tm.x);   // sm + i*tm
}
// inverse 4-pt DFT (W4 = +i)
__device__ __forceinline__ void dft4i(float2 x0, float2 x1, float2 x2, float2 x3,
                                      float2& y0, float2& y1, float2& y2, float2& y3) {
    float2 sp = make_float2(x0.x + x2.x, x0.y + x2.y);
    float2 sm = make_float2(x0.x - x2.x, x0.y - x2.y);
    float2 tp = make_float2(x1.x + x3.x, x1.y + x3.y);
    float2 tm = make_float2(x1.x - x3.x, x1.y - x3.y);
    y0 = make_float2(sp.x + tp.x, sp.y + tp.y);
    y2 = make_float2(sp.x - tp.x, sp.y - tp.y);
    y1 = make_float2(sm.x - tm.y, sm.y + tm.x);   // sm + i*tm
    y3 = make_float2(sm.x + tm.y, sm.y - tm.x);   // sm - i*tm
}

// 16-pt DFT in registers, natural order in/out. fwd: e^{-2pi i a f/16}
__device__ __forceinline__ void dft16f(float2* v) {
    const float2 W[10] = {
        { 1.f, 0.f}, { C16,-S16}, { R22,-R22}, { S16,-C16}, { 0.f,-1.f},
        {-S16,-C16}, {-R22,-R22}, {-C16,-S16}, {-1.f, 0.f}, {-C16, S16}
    };
    float2 u[16];
    #pragma unroll
    for (int a0 = 0; a0 < 4; ++a0) {
        float2 t0, t1, t2, t3;
        dft4f(v[a0], v[a0 + 4], v[a0 + 8], v[a0 + 12], t0, t1, t2, t3);
        u[a0 * 4 + 0] = t0;
        u[a0 * 4 + 1] = cmul(t1, W[a0]);
        u[a0 * 4 + 2] = cmul(t2, W[2 * a0]);
        u[a0 * 4 + 3] = cmul(t3, W[3 * a0]);
    }
    #pragma unroll
    for (int fl = 0; fl < 4; ++fl) {
        float2 y0, y1, y2, y3;
        dft4f(u[0 * 4 + fl], u[1 * 4 + fl], u[2 * 4 + fl], u[3 * 4 + fl], y0, y1, y2, y3);
        v[fl]      = y0;
        v[fl + 4]  = y1;
        v[fl + 8]  = y2;
        v[fl + 12] = y3;
    }
}
// inverse 16-pt: e^{+2pi i a f/16}, unnormalized
__device__ __forceinline__ void dft16i(float2* v) {
    const float2 W[10] = {
        { 1.f, 0.f}, { C16, S16}, { R22, R22}, { S16, C16}, { 0.f, 1.f},
        {-S16, C16}, {-R22, R22}, {-C16, S16}, {-1.f, 0.f}, {-C16,-S16}
    };
    float2 u[16];
    #pragma unroll
    for (int fl = 0; fl < 4; ++fl) {
        float2 t0, t1, t2, t3;
        dft4i(v[fl], v[fl + 4], v[fl + 8], v[fl + 12], t0, t1, t2, t3);
        u[fl * 4 + 0] = t0;
        u[fl * 4 + 1] = cmul(t1, W[fl]);
        u[fl * 4 + 2] = cmul(t2, W[2 * fl]);
        u[fl * 4 + 3] = cmul(t3, W[3 * fl]);
    }
    #pragma unroll
    for (int a0 = 0; a0 < 4; ++a0) {
        float2 y0, y1, y2, y3;
        dft4i(u[0 * 4 + a0], u[1 * 4 + a0], u[2 * 4 + a0], u[3 * 4 + a0], y0, y1, y2, y3);
        v[a0]      = y0;
        v[a0 + 4]  = y1;
        v[a0 + 8]  = y2;
        v[a0 + 12] = y3;
    }
}

// W64^mp twiddle, mp in [0,4), via select chain (no MUFU)
__device__ __forceinline__ float2 w64(int mp, float sgn) {
    float c = (mp == 0) ? 1.0f
            : (mp == 1) ? 0.99518472667219693f
            : (mp == 2) ? 0.98078528040323044f
            :             0.95694033573220882f;
    float s = (mp == 0) ? 0.0f
            : (mp == 1) ? 0.09801714032956060f
            : (mp == 2) ? 0.19509032201612827f
            :             0.29028467725446233f;
    return make_float2(c, sgn * s);
}

extern __shared__ float2 smem_dyn[];

__global__ void __launch_bounds__(NTHREADS, 1) autocorr_fused_kernel(
    const float* __restrict__ Q, const float* __restrict__ K,
    const float* __restrict__ V, float* __restrict__ out)
{
    float2* z = smem_dyn;                       // [CHB][ZS]
    float*  vf = (float*)(smem_dyn + CHB * ZS); // [CHB][VSTR]
    __shared__ float2 cand[CHB][2][2];
    __shared__ float  w_sh[CHB][TOPK + 1];
    __shared__ int    i_sh[CHB][TOPK];

    const int tid = threadIdx.x;
    const int ch  = tid >> 6;
    const int u   = tid & 63;
    float2* zc = z + ch * ZS;

    const int bc0 = blockIdx.x * CHB;
    const int b   = bc0 >> 9;
    const int c0  = bc0 & (DM - 1);
    const size_t base = (size_t)b * SEQL * DM + c0;

    // ---- load: z = q + i*k (swizzled), prefetch V ----
    for (int idx = tid; idx < 2048; idx += NTHREADS) {
        int t  = idx >> 1;
        int d0 = (idx & 1) << 2;
        size_t off = base + (size_t)t * DM + d0;
        float4 q4 = *(const float4*)(Q + off);
        float4 k4 = *(const float4*)(K + off);
        int st = sw(t);
        z[(d0 + 0) * ZS + st] = make_float2(q4.x, k4.x);
        z[(d0 + 1) * ZS + st] = make_float2(q4.y, k4.y);
        z[(d0 + 2) * ZS + st] = make_float2(q4.z, k4.z);
        z[(d0 + 3) * ZS + st] = make_float2(q4.w, k4.w);
        float4 v4 = *(const float4*)(V + off);
        vf[(d0 + 0) * VSTR + t] = v4.x;
        vf[(d0 + 1) * VSTR + t] = v4.y;
        vf[(d0 + 2) * VSTR + t] = v4.z;
        vf[(d0 + 3) * VSTR + t] = v4.w;
    }
    __syncthreads();

    // ---- P1: radix-16 over stride 64, twiddle W1024^{u*f0} ----
    {
        float2 v[16];
        #pragma unroll
        for (int a = 0; a < 16; ++a) v[a] = zc[sw(u + 64 * a)];
        dft16f(v);
        float s, c;
        sincospif((float)u * (1.0f / 512.0f), &s, &c);
        float2 W[16];
        twpow(make_float2(c, -s), W);
        #pragma unroll
        for (int f = 1; f < 16; ++f) v[f] = cmul(v[f], W[f]);
        #pragma unroll
        for (int f = 0; f < 16; ++f) zc[sw(u + 64 * f)] = v[f];
    }
    __syncthreads();

    // ---- P2: radix-16 over stride 4 within 64-blocks, twiddle W64^{m'*f1} ----
    {
        const int blk = u >> 2;
        const int mp  = u & 3;
        const int bas = 64 * blk + mp;
        float2 v[16];
        #pragma unroll
        for (int a = 0; a < 16; ++a) v[a] = zc[sw(bas + 4 * a)];
        dft16f(v);
        float2 W[16];
        twpow(w64(mp, -1.0f), W);
        #pragma unroll
        for (int f = 1; f < 16; ++f) v[f] = cmul(v[f], W[f]);
        #pragma unroll
        for (int f = 0; f < 16; ++f) zc[sw(bas + 4 * f)] = v[f];
    }
    __syncthreads();

    // ---- FUSED: fwd radix-4 + cross-spectrum + inv radix-4, all in registers ----
    // After P2, quad at swizzled addrs sw(4g)^k (g = digitswap(c)) holds the
    // 4-pt pre-DFT values whose DFT gives Z[c + 256k] at slot k.
    // Mirror frequencies 1024-f live in quad c' = 256-c at slot 3-k.
    // NOTE: sw(4g+k) == sw(4g) ^ k because the XOR key depends only on bits >= 4.
    {
        const float scl = 1.0f / (float)SEQL;
        #pragma unroll
        for (int unit = 0; unit < 2; ++unit) {
            int c = u + 1 + unit * 64;          // [1,64] / [65,128]
            if (c < 128) {
                int cp = 256 - c;
                int pA = sw((((c  & 15) << 4) | (c  >> 4)) << 2);
                int pB = sw((((cp & 15) << 4) | (cp >> 4)) << 2);
                float2 A[4], B[4];
                dft4f(zc[pA], zc[pA^1], zc[pA^2], zc[pA^3], A[0], A[1], A[2], A[3]);
                dft4f(zc[pB], zc[pB^1], zc[pB^2], zc[pB^3], B[0], B[1], B[2], B[3]);
                #pragma unroll
                for (int k = 0; k < 4; ++k) {
                    float2 Zf = A[k], Zp = B[3 - k];
                    float Qx = 0.5f * (Zf.x + Zp.x), Qy = 0.5f * (Zf.y - Zp.y);
                    float Kx = 0.5f * (Zf.y + Zp.y), Ky = -0.5f * (Zf.x - Zp.x);
                    float Px = (Qx * Kx + Qy * Ky) * scl;
                    float Py = (Qy * Kx - Qx * Ky) * scl;
                    A[k]     = make_float2(Px,  Py);
                    B[3 - k] = make_float2(Px, -Py);
                }
                float2 y0, y1, y2, y3;
                dft4i(A[0], A[1], A[2], A[3], y0, y1, y2, y3);
                zc[pA] = y0; zc[pA^1] = y1; zc[pA^2] = y2; zc[pA^3] = y3;
                dft4i(B[0], B[1], B[2], B[3], y0, y1, y2, y3);
                zc[pB] = y0; zc[pB^1] = y1; zc[pB^2] = y2; zc[pB^3] = y3;
            } else {
                // u==63, unit==1: c=128 self-paired quad (g=8, p=32)
                {
                    int pA = sw(32);
                    float2 A[4];
                    dft4f(zc[pA], zc[pA^1], zc[pA^2], zc[pA^3], A[0], A[1], A[2], A[3]);
                    #pragma unroll
                    for (int k = 0; k < 2; ++k) {
                        float2 Zf = A[k], Zp = A[3 - k];
                        float Qx = 0.5f * (Zf.x + Zp.x), Qy = 0.5f * (Zf.y - Zp.y);
                        float Kx = 0.5f * (Zf.y + Zp.y), Ky = -0.5f * (Zf.x - Zp.x);
                        float Px = (Qx * Kx + Qy * Ky) * scl;
                        float Py = (Qy * Kx - Qx * Ky) * scl;
                        A[k]     = make_float2(Px,  Py);
                        A[3 - k] = make_float2(Px, -Py);
                    }
                    float2 y0, y1, y2, y3;
                    dft4i(A[0], A[1], A[2], A[3], y0, y1, y2, y3);
                    zc[pA] = y0; zc[pA^1] = y1; zc[pA^2] = y2; zc[pA^3] = y3;
                }
                // c=0 quad (g=0, p=0, sw key 0): f={0,256,512,768}
                {
                    float2 A[4];
                    dft4f(zc[0], zc[1], zc[2], zc[3], A[0], A[1], A[2], A[3]);
                    A[0] = make_float2(A[0].x * A[0].y * scl, 0.0f);
                    A[2] = make_float2(A[2].x * A[2].y * scl, 0.0f);
                    {
                        float2 Zf = A[1], Zp = A[3];
                        float Qx = 0.5f * (Zf.x + Zp.x), Qy = 0.5f * (Zf.y - Zp.y);
                        float Kx = 0.5f * (Zf.y + Zp.y), Ky = -0.5f * (Zf.x - Zp.x);
                        float Px = (Qx * Kx + Qy * Ky) * scl;
                        float Py = (Qy * Kx - Qx * Ky) * scl;
                        A[1] = make_float2(Px,  Py);
                        A[3] = make_float2(Px, -Py);
                    }
                    float2 y0, y1, y2, y3;
                    dft4i(A[0], A[1], A[2], A[3], y0, y1, y2, y3);
                    zc[0] = y0; zc[1] = y1; zc[2] = y2; zc[3] = y3;
                }
            }
        }
    }
    __syncthreads();

    // ---- IP2: conj twiddle then inverse radix-16 stride 4 ----
    {
        const int blk = u >> 2;
        const int mp  = u & 3;
        const int bas = 64 * blk + mp;
        float2 v[16];
        #pragma unroll
        for (int f = 0; f < 16; ++f) v[f] = zc[sw(bas + 4 * f)];
        float2 W[16];
        twpow(w64(mp, 1.0f), W);
        #pragma unroll
        for (int f = 1; f < 16; ++f) v[f] = cmul(v[f], W[f]);
        dft16i(v);
        #pragma unroll
        for (int a = 0; a < 16; ++a) zc[sw(bas + 4 * a)] = v[a];
    }
    __syncthreads();

    // ---- IP1: conj twiddle then inverse radix-16 stride 64; results stay in regs ----
    float re[16];
    {
        float2 v[16];
        #pragma unroll
        for (int f = 0; f < 16; ++f) v[f] = zc[sw(u + 64 * f)];
        float s, c;
        sincospif((float)u * (1.0f / 512.0f), &s, &c);
        float2 W[16];
        twpow(make_float2(c, s), W);
        #pragma unroll
        for (int f = 1; f < 16; ++f) v[f] = cmul(v[f], W[f]);
        dft16i(v);
        #pragma unroll
        for (int a = 0; a < 16; ++a) re[a] = v[a].x;   // time index = u + 64a
    }

    // ---- top-13: register-resident, 2 warps per channel, named barriers ----
    {
        const int lane = tid & 31;
        const int wih  = (u >> 5) & 1;
        float lv = re[0]; int lj = 0;
        #pragma unroll
        for (int j2 = 1; j2 < 16; ++j2)
            if (re[j2] > lv) { lv = re[j2]; lj = j2; }
        int li = u + 64 * lj;

        #pragma unroll 1
        for (int r = 0; r < TOPK; ++r) {
            float bv = lv; int bi = li;
            #pragma unroll
            for (int off = 16; off; off >>= 1) {
                float ov = __shfl_down_sync(0xffffffffu, bv, off);
                int   oi = __shfl_down_sync(0xffffffffu, bi, off);
                if (ov > bv || (ov == bv && oi < bi)) { bv = ov; bi = oi; }
            }
            bv = __shfl_sync(0xffffffffu, bv, 0);
            bi = __shfl_sync(0xffffffffu, bi, 0);
            int par = r & 1;
            if (lane == 0)
                cand[ch][wih][par] = make_float2(bv, __int_as_float(bi));
            asm volatile("bar.sync %0, %1;" :: "r"(ch + 1), "r"(64) : "memory");
            float2 c0v = cand[ch][0][par];
            float2 c1v = cand[ch][1][par];
            float wv; int wi;
            int i0 = __float_as_int(c0v.y), i1 = __float_as_int(c1v.y);
            if (c1v.x > c0v.x || (c1v.x == c0v.x && i1 < i0)) { wv = c1v.x; wi = i1; }
            else                                              { wv = c0v.x; wi = i0; }
            if (u == 0) { w_sh[ch][r] = wv; i_sh[ch][r] = wi; }
            if ((wi & 63) == u) {
                re[wi >> 6] = -INFINITY;
                lv = re[0]; lj = 0;
                #pragma unroll
                for (int j2 = 1; j2 < 16; ++j2)
                    if (re[j2] > lv) { lv = re[j2]; lj = j2; }
                li = u + 64 * lj;
            }
        }
        asm volatile("bar.sync %0, %1;" :: "r"(ch + 1), "r"(64) : "memory");
        if (u == 0) {
            float m = -INFINITY;
            #pragma unroll
            for (int i = 0; i < TOPK; ++i) m = fmaxf(m, w_sh[ch][i]);
            float e[TOPK]; float ssum = 0.0f;
            #pragma unroll
            for (int i = 0; i < TOPK; ++i) { e[i] = expf(w_sh[ch][i] - m); ssum += e[i]; }
            float inv = 1.0f / ssum;
            #pragma unroll
            for (int i = 0; i < TOPK; ++i) w_sh[ch][i] = e[i] * inv;
        }
    }
    __syncthreads();

    // ---- time-delay aggregation ----
    {
        const int d    = tid & 7;
        const int slot = tid >> 3;
        float wr[TOPK];
        int   ir[TOPK];
        #pragma unroll
        for (int i = 0; i < TOPK; ++i) { wr[i] = w_sh[d][i]; ir[i] = i_sh[d][i]; }
        const float* vc = vf + d * VSTR;
        #pragma unroll
        for (int i0 = 0; i0 < 16; i0 += 4) {
            int t = (slot << 4) + i0;
            float a0 = 0.f, a1 = 0.f, a2 = 0.f, a3 = 0.f;
            #pragma unroll
            for (int i = 0; i < TOPK; ++i) {
                int r = ir[i] + t;
                a0 = fmaf(wr[i], vc[min(r,     SEQL - 1)], a0);
                a1 = fmaf(wr[i], vc[min(r + 1, SEQL - 1)], a1);
                a2 = fmaf(wr[i], vc[min(r + 2, SEQL - 1)], a2);
                a3 = fmaf(wr[i], vc[min(r + 3, SEQL - 1)], a3);
            }
            size_t o = base + (size_t)t * DM + d;
            out[o]          = a0;
            out[o + DM]     = a1;
            out[o + 2 * DM] = a2;
            out[o + 3 * DM] = a3;
        }
    }
}

extern "C" void kernel_launch(void* const* d_in, const int* in_sizes, int n_in,
                              void* d_out, int out_size)
{
    const float* Q = (const float*)d_in[0];
    const float* K = (const float*)d_in[1];
    const float* V = (const float*)d_in[2];
    float* out = (float*)d_out;

    const size_t smem = (size_t)(CHB * ZS) * sizeof(float2)
                      + (size_t)(CHB * VSTR) * sizeof(float);   // 98,496 B
    cudaFuncSetAttribute(autocorr_fused_kernel,
                         cudaFuncAttributeMaxDynamicSharedMemorySize, (int)smem);
    autocorr_fused_kernel<<<NCH / CHB, NTHREADS, smem>>>(Q, K, V, out);
}

// round 7
// speedup vs baseline: 1.9134x; 1.1139x over previous
#include <cuda_runtime.h>
#include <math.h>

#define DM      512
#define SEQL    1024
#define NCH     8192
#define CHB     8
#define TOPK    13
#define NTHREADS 512
#define ZS      1025      // float2 stride per channel
#define VSTR    1028      // padded float stride for V tile
#define OTS     2050      // float stride for output staging (== ZS*2)

__device__ __forceinline__ float2 cmul(float2 a, float2 b) {
    return make_float2(a.x * b.x - a.y * b.y, a.x * b.y + a.y * b.x);
}
// XOR swizzle within a 1024-element channel region
__device__ __forceinline__ int sw(int p) { return p ^ ((p >> 4) & 15); }

// powers W[1..15] from w1 via squaring chain
__device__ __forceinline__ void twpow(float2 w1, float2* W) {
    W[1] = w1;
    W[2] = cmul(w1, w1);
    W[4] = cmul(W[2], W[2]);
    W[8] = cmul(W[4], W[4]);
    W[3] = cmul(W[2], W[1]);
    W[5] = cmul(W[4], W[1]);
    W[6] = cmul(W[4], W[2]);
    W[7] = cmul(W[4], W[3]);
    W[9]  = cmul(W[8], W[1]);
    W[10] = cmul(W[8], W[2]);
    W[11] = cmul(W[8], W[3]);
    W[12] = cmul(W[8], W[4]);
    W[13] = cmul(W[8], W[5]);
    W[14] = cmul(W[8], W[6]);
    W[15] = cmul(W[8], W[7]);
}

#define C16 0.9238795325112867f
#define S16 0.3826834323650898f
#define R22 0.7071067811865476f

// forward 4-pt DFT (W4 = -i)
__device__ __forceinline__ void dft4f(float2 x0, float2 x1, float2 x2, float2 x3,
                                      float2& y0, float2& y1, float2& y2, float2& y3) {
    float2 sp = make_float2(x0.x + x2.x, x0.y + x2.y);
    float2 sm = make_float2(x0.x - x2.x, x0.y - x2.y);
    float2 tp = make_float2(x1.x + x3.x, x1.y + x3.y);
    float2 tm = make_float2(x1.x - x3.x, x1.y - x3.y);
    y0 = make_float2(sp.x + tp.x, sp.y + tp.y);
    y2 = make_float2(sp.x - tp.x, sp.y - tp.y);
    y1 = make_float2(sm.x + tm.y, sm.y - tm.x);   // sm - i*tm
    y3 = make_float2(sm.x - tm.y, sm.y + tm.x);   // sm + i*tm
}
// inverse 4-pt DFT (W4 = +i)
__device__ __forceinline__ void dft4i(float2 x0, float2 x1, float2 x2, float2 x3,
                                      float2& y0, float2& y1, float2& y2, float2& y3) {
    float2 sp = make_float2(x0.x + x2.x, x0.y + x2.y);
    float2 sm = make_float2(x0.x - x2.x, x0.y - x2.y);
    float2 tp = make_float2(x1.x + x3.x, x1.y + x3.y);
    float2 tm = make_float2(x1.x - x3.x, x1.y - x3.y);
    y0 = make_float2(sp.x + tp.x, sp.y + tp.y);
    y2 = make_float2(sp.x - tp.x, sp.y - tp.y);
    y1 = make_float2(sm.x - tm.y, sm.y + tm.x);   // sm + i*tm
    y3 = make_float2(sm.x + tm.y, sm.y - tm.x);   // sm - i*tm
}

// 16-pt DFT in registers, natural order in/out. fwd: e^{-2pi i a f/16}
__device__ __forceinline__ void dft16f(float2* v) {
    const float2 W[10] = {
        { 1.f, 0.f}, { C16,-S16}, { R22,-R22}, { S16,-C16}, { 0.f,-1.f},
        {-S16,-C16}, {-R22,-R22}, {-C16,-S16}, {-1.f, 0.f}, {-C16, S16}
    };
    float2 u[16];
    #pragma unroll
    for (int a0 = 0; a0 < 4; ++a0) {
        float2 t0, t1, t2, t3;
        dft4f(v[a0], v[a0 + 4], v[a0 + 8], v[a0 + 12], t0, t1, t2, t3);
        u[a0 * 4 + 0] = t0;
        u[a0 * 4 + 1] = cmul(t1, W[a0]);
        u[a0 * 4 + 2] = cmul(t2, W[2 * a0]);
        u[a0 * 4 + 3] = cmul(t3, W[3 * a0]);
    }
    #pragma unroll
    for (int fl = 0; fl < 4; ++fl) {
        float2 y0, y1, y2, y3;
        dft4f(u[0 * 4 + fl], u[1 * 4 + fl], u[2 * 4 + fl], u[3 * 4 + fl], y0, y1, y2, y3);
        v[fl]      = y0;
        v[fl + 4]  = y1;
        v[fl + 8]  = y2;
        v[fl + 12] = y3;
    }
}
// inverse 16-pt: e^{+2pi i a f/16}, unnormalized
__device__ __forceinline__ void dft16i(float2* v) {
    const float2 W[10] = {
        { 1.f, 0.f}, { C16, S16}, { R22, R22}, { S16, C16}, { 0.f, 1.f},
        {-S16, C16}, {-R22, R22}, {-C16, S16}, {-1.f, 0.f}, {-C16,-S16}
    };
    float2 u[16];
    #pragma unroll
    for (int fl = 0; fl < 4; ++fl) {
        float2 t0, t1, t2, t3;
        dft4i(v[fl], v[fl + 4], v[fl + 8], v[fl + 12], t0, t1, t2, t3);
        u[fl * 4 + 0] = t0;
        u[fl * 4 + 1] = cmul(t1, W[fl]);
        u[fl * 4 + 2] = cmul(t2, W[2 * fl]);
        u[fl * 4 + 3] = cmul(t3, W[3 * fl]);
    }
    #pragma unroll
    for (int a0 = 0; a0 < 4; ++a0) {
        float2 y0, y1, y2, y3;
        dft4i(u[0 * 4 + a0], u[1 * 4 + a0], u[2 * 4 + a0], u[3 * 4 + a0], y0, y1, y2, y3);
        v[a0]      = y0;
        v[a0 + 4]  = y1;
        v[a0 + 8]  = y2;
        v[a0 + 12] = y3;
    }
}

// W64^mp twiddle, mp in [0,4), via select chain (no MUFU)
__device__ __forceinline__ float2 w64(int mp, float sgn) {
    float c = (mp == 0) ? 1.0f
            : (mp == 1) ? 0.99518472667219693f
            : (mp == 2) ? 0.98078528040323044f
            :             0.95694033573220882f;
    float s = (mp == 0) ? 0.0f
            : (mp == 1) ? 0.09801714032956060f
            : (mp == 2) ? 0.19509032201612827f
            :             0.29028467725446233f;
    return make_float2(c, sgn * s);
}

extern __shared__ float2 smem_dyn[];

__global__ void __launch_bounds__(NTHREADS, 1) autocorr_fused_kernel(
    const float* __restrict__ Q, const float* __restrict__ K,
    const float* __restrict__ V, float* __restrict__ out)
{
    float2* z = smem_dyn;                       // [CHB][ZS]
    float*  vf = (float*)(smem_dyn + CHB * ZS); // [CHB][VSTR]
    __shared__ float2 cand[CHB][2][2];
    __shared__ float  w_sh[CHB][TOPK + 1];
    __shared__ int    i_sh[CHB][TOPK];

    const int tid = threadIdx.x;
    const int ch  = tid >> 6;
    const int u   = tid & 63;
    float2* zc = z + ch * ZS;

    const int bc0 = blockIdx.x * CHB;
    const int b   = bc0 >> 9;
    const int c0  = bc0 & (DM - 1);
    const size_t base = (size_t)b * SEQL * DM + c0;

    // ---- load: z = q + i*k (swizzled), prefetch V ----
    for (int idx = tid; idx < 2048; idx += NTHREADS) {
        int t  = idx >> 1;
        int d0 = (idx & 1) << 2;
        size_t off = base + (size_t)t * DM + d0;
        float4 q4 = *(const float4*)(Q + off);
        float4 k4 = *(const float4*)(K + off);
        int st = sw(t);
        z[(d0 + 0) * ZS + st] = make_float2(q4.x, k4.x);
        z[(d0 + 1) * ZS + st] = make_float2(q4.y, k4.y);
        z[(d0 + 2) * ZS + st] = make_float2(q4.z, k4.z);
        z[(d0 + 3) * ZS + st] = make_float2(q4.w, k4.w);
        float4 v4 = *(const float4*)(V + off);
        vf[(d0 + 0) * VSTR + t] = v4.x;
        vf[(d0 + 1) * VSTR + t] = v4.y;
        vf[(d0 + 2) * VSTR + t] = v4.z;
        vf[(d0 + 3) * VSTR + t] = v4.w;
    }
    __syncthreads();

    // ---- P1: radix-16 over stride 64, twiddle W1024^{u*f0} ----
    {
        float2 v[16];
        #pragma unroll
        for (int a = 0; a < 16; ++a) v[a] = zc[sw(u + 64 * a)];
        dft16f(v);
        float s, c;
        sincospif((float)u * (1.0f / 512.0f), &s, &c);
        float2 W[16];
        twpow(make_float2(c, -s), W);
        #pragma unroll
        for (int f = 1; f < 16; ++f) v[f] = cmul(v[f], W[f]);
        #pragma unroll
        for (int f = 0; f < 16; ++f) zc[sw(u + 64 * f)] = v[f];
    }
    __syncthreads();

    // ---- P2: radix-16 over stride 4 within 64-blocks, twiddle W64^{m'*f1} ----
    {
        const int blk = u >> 2;
        const int mp  = u & 3;
        const int bas = 64 * blk + mp;
        float2 v[16];
        #pragma unroll
        for (int a = 0; a < 16; ++a) v[a] = zc[sw(bas + 4 * a)];
        dft16f(v);
        float2 W[16];
        twpow(w64(mp, -1.0f), W);
        #pragma unroll
        for (int f = 1; f < 16; ++f) v[f] = cmul(v[f], W[f]);
        #pragma unroll
        for (int f = 0; f < 16; ++f) zc[sw(bas + 4 * f)] = v[f];
    }
    __syncthreads();

    // ---- FUSED: fwd radix-4 + cross-spectrum + inv radix-4, all in registers ----
    {
        const float scl = 1.0f / (float)SEQL;
        #pragma unroll
        for (int unit = 0; unit < 2; ++unit) {
            int c = u + 1 + unit * 64;          // [1,64] / [65,128]
            if (c < 128) {
                int cp = 256 - c;
                int pA = sw((((c  & 15) << 4) | (c  >> 4)) << 2);
                int pB = sw((((cp & 15) << 4) | (cp >> 4)) << 2);
                float2 A[4], B[4];
                dft4f(zc[pA], zc[pA^1], zc[pA^2], zc[pA^3], A[0], A[1], A[2], A[3]);
                dft4f(zc[pB], zc[pB^1], zc[pB^2], zc[pB^3], B[0], B[1], B[2], B[3]);
                #pragma unroll
                for (int k = 0; k < 4; ++k) {
                    float2 Zf = A[k], Zp = B[3 - k];
                    float Qx = 0.5f * (Zf.x + Zp.x), Qy = 0.5f * (Zf.y - Zp.y);
                    float Kx = 0.5f * (Zf.y + Zp.y), Ky = -0.5f * (Zf.x - Zp.x);
                    float Px = (Qx * Kx + Qy * Ky) * scl;
                    float Py = (Qy * Kx - Qx * Ky) * scl;
                    A[k]     = make_float2(Px,  Py);
                    B[3 - k] = make_float2(Px, -Py);
                }
                float2 y0, y1, y2, y3;
                dft4i(A[0], A[1], A[2], A[3], y0, y1, y2, y3);
                zc[pA] = y0; zc[pA^1] = y1; zc[pA^2] = y2; zc[pA^3] = y3;
                dft4i(B[0], B[1], B[2], B[3], y0, y1, y2, y3);
                zc[pB] = y0; zc[pB^1] = y1; zc[pB^2] = y2; zc[pB^3] = y3;
            } else {
                // u==63, unit==1: c=128 self-paired quad (g=8, p=32)
                {
                    int pA = sw(32);
                    float2 A[4];
                    dft4f(zc[pA], zc[pA^1], zc[pA^2], zc[pA^3], A[0], A[1], A[2], A[3]);
                    #pragma unroll
                    for (int k = 0; k < 2; ++k) {
                        float2 Zf = A[k], Zp = A[3 - k];
                        float Qx = 0.5f * (Zf.x + Zp.x), Qy = 0.5f * (Zf.y - Zp.y);
                        float Kx = 0.5f * (Zf.y + Zp.y), Ky = -0.5f * (Zf.x - Zp.x);
                        float Px = (Qx * Kx + Qy * Ky) * scl;
                        float Py = (Qy * Kx - Qx * Ky) * scl;
                        A[k]     = make_float2(Px,  Py);
                        A[3 - k] = make_float2(Px, -Py);
                    }
                    float2 y0, y1, y2, y3;
                    dft4i(A[0], A[1], A[2], A[3], y0, y1, y2, y3);
                    zc[pA] = y0; zc[pA^1] = y1; zc[pA^2] = y2; zc[pA^3] = y3;
                }
                // c=0 quad (g=0, p=0, sw key 0): f={0,256,512,768}
                {
                    float2 A[4];
                    dft4f(zc[0], zc[1], zc[2], zc[3], A[0], A[1], A[2], A[3]);
                    A[0] = make_float2(A[0].x * A[0].y * scl, 0.0f);
                    A[2] = make_float2(A[2].x * A[2].y * scl, 0.0f);
                    {
                        float2 Zf = A[1], Zp = A[3];
                        float Qx = 0.5f * (Zf.x + Zp.x), Qy = 0.5f * (Zf.y - Zp.y);
                        float Kx = 0.5f * (Zf.y + Zp.y), Ky = -0.5f * (Zf.x - Zp.x);
                        float Px = (Qx * Kx + Qy * Ky) * scl;
                        float Py = (Qy * Kx - Qx * Ky) * scl;
                        A[1] = make_float2(Px,  Py);
                        A[3] = make_float2(Px, -Py);
                    }
                    float2 y0, y1, y2, y3;
                    dft4i(A[0], A[1], A[2], A[3], y0, y1, y2, y3);
                    zc[0] = y0; zc[1] = y1; zc[2] = y2; zc[3] = y3;
                }
            }
        }
    }
    __syncthreads();

    // ---- IP2: conj twiddle then inverse radix-16 stride 4 ----
    {
        const int blk = u >> 2;
        const int mp  = u & 3;
        const int bas = 64 * blk + mp;
        float2 v[16];
        #pragma unroll
        for (int f = 0; f < 16; ++f) v[f] = zc[sw(bas + 4 * f)];
        float2 W[16];
        twpow(w64(mp, 1.0f), W);
        #pragma unroll
        for (int f = 1; f < 16; ++f) v[f] = cmul(v[f], W[f]);
        dft16i(v);
        #pragma unroll
        for (int a = 0; a < 16; ++a) zc[sw(bas + 4 * a)] = v[a];
    }
    __syncthreads();

    // ---- IP1: conj twiddle then inverse radix-16 stride 64; results stay in regs ----
    float re[16];
    {
        float2 v[16];
        #pragma unroll
        for (int f = 0; f < 16; ++f) v[f] = zc[sw(u + 64 * f)];
        float s, c;
        sincospif((float)u * (1.0f / 512.0f), &s, &c);
        float2 W[16];
        twpow(make_float2(c, s), W);
        #pragma unroll
        for (int f = 1; f < 16; ++f) v[f] = cmul(v[f], W[f]);
        dft16i(v);
        #pragma unroll
        for (int a = 0; a < 16; ++a) re[a] = v[a].x;   // time index = u + 64a
    }

    // ---- top-13: register-resident, 2 warps per channel, named barriers ----
    {
        const int lane = tid & 31;
        const int wih  = (u >> 5) & 1;
        float lv = re[0]; int lj = 0;
        #pragma unroll
        for (int j2 = 1; j2 < 16; ++j2)
            if (re[j2] > lv) { lv = re[j2]; lj = j2; }
        int li = u + 64 * lj;

        #pragma unroll 1
        for (int r = 0; r < TOPK; ++r) {
            float bv = lv; int bi = li;
            #pragma unroll
            for (int off = 16; off; off >>= 1) {
                float ov = __shfl_down_sync(0xffffffffu, bv, off);
                int   oi = __shfl_down_sync(0xffffffffu, bi, off);
                if (ov > bv || (ov == bv && oi < bi)) { bv = ov; bi = oi; }
            }
            bv = __shfl_sync(0xffffffffu, bv, 0);
            bi = __shfl_sync(0xffffffffu, bi, 0);
            int par = r & 1;
            if (lane == 0)
                cand[ch][wih][par] = make_float2(bv, __int_as_float(bi));
            asm volatile("bar.sync %0, %1;" :: "r"(ch + 1), "r"(64) : "memory");
            float2 c0v = cand[ch][0][par];
            float2 c1v = cand[ch][1][par];
            float wv; int wi;
            int i0 = __float_as_int(c0v.y), i1 = __float_as_int(c1v.y);
            if (c1v.x > c0v.x || (c1v.x == c0v.x && i1 < i0)) { wv = c1v.x; wi = i1; }
            else                                              { wv = c0v.x; wi = i0; }
            if (u == 0) { w_sh[ch][r] = wv; i_sh[ch][r] = wi; }
            if ((wi & 63) == u) {
                re[wi >> 6] = -INFINITY;
                lv = re[0]; lj = 0;
                #pragma unroll
                for (int j2 = 1; j2 < 16; ++j2)
                    if (re[j2] > lv) { lv = re[j2]; lj = j2; }
                li = u + 64 * lj;
            }
        }
        asm volatile("bar.sync %0, %1;" :: "r"(ch + 1), "r"(64) : "memory");
        if (u == 0) {
            float m = -INFINITY;
            #pragma unroll
            for (int i = 0; i < TOPK; ++i) m = fmaxf(m, w_sh[ch][i]);
            float e[TOPK]; float ssum = 0.0f;
            #pragma unroll
            for (int i = 0; i < TOPK; ++i) { e[i] = expf(w_sh[ch][i] - m); ssum += e[i]; }
            float inv = 1.0f / ssum;
            #pragma unroll
            for (int i = 0; i < TOPK; ++i) w_sh[ch][i] = e[i] * inv;
        }
    }
    __syncthreads();   // all IP1 reads of z done; z is now free for output staging

    // ---- time-delay aggregation: warp-uniform taps, conflict-free reads ----
    // Thread u of channel ch handles t = u + 64*j. All lanes of a warp share
    // the channel -> taps are broadcast; per tap, 32 lanes read 32 consecutive
    // vf floats -> zero bank conflicts. Results staged in z (as floats).
    float* ot = (float*)z;                      // [CHB][OTS] floats
    {
        float wr[TOPK];
        int   ir[TOPK];
        #pragma unroll
        for (int i = 0; i < TOPK; ++i) { wr[i] = w_sh[ch][i]; ir[i] = i_sh[ch][i]; }
        const float* vc = vf + ch * VSTR;
        float* oc = ot + ch * OTS;
        #pragma unroll
        for (int j = 0; j < 16; j += 4) {
            int t0 = u + 64 * j;
            float a0 = 0.f, a1 = 0.f, a2 = 0.f, a3 = 0.f;
            #pragma unroll
            for (int i = 0; i < TOPK; ++i) {
                int r = ir[i] + t0;
                a0 = fmaf(wr[i], vc[min(r,       SEQL - 1)], a0);
                a1 = fmaf(wr[i], vc[min(r + 64,  SEQL - 1)], a1);
                a2 = fmaf(wr[i], vc[min(r + 128, SEQL - 1)], a2);
                a3 = fmaf(wr[i], vc[min(r + 192, SEQL - 1)], a3);
            }
            oc[t0]       = a0;
            oc[t0 + 64]  = a1;
            oc[t0 + 128] = a2;
            oc[t0 + 192] = a3;
        }
    }
    __syncthreads();

    // ---- coalesced float4 write-out from the staging tile ----
    for (int idx = tid; idx < 2048; idx += NTHREADS) {
        int t  = idx >> 1;
        int d0 = (idx & 1) << 2;
        float4 o4;
        o4.x = ot[(d0 + 0) * OTS + t];
        o4.y = ot[(d0 + 1) * OTS + t];
        o4.z = ot[(d0 + 2) * OTS + t];
        o4.w = ot[(d0 + 3) * OTS + t];
        *(float4*)(out + base + (size_t)t * DM + d0) = o4;
    }
}

extern "C" void kernel_launch(void* const* d_in, const int* in_sizes, int n_in,
                              void* d_out, int out_size)
{
    const float* Q = (const float*)d_in[0];
    const float* K = (const float*)d_in[1];
    const float* V = (const float*)d_in[2];
    float* out = (float*)d_out;

    const size_t smem = (size_t)(CHB * ZS) * sizeof(float2)
                      + (size_t)(CHB * VSTR) * sizeof(float);   // 98,496 B
    cudaFuncSetAttribute(autocorr_fused_kernel,
                         cudaFuncAttributeMaxDynamicSharedMemorySize, (int)smem);
    autocorr_fused_kernel<<<NCH / CHB, NTHREADS, smem>>>(Q, K, V, out);
}